// round 15
// baseline (speedup 1.0000x reference)
#include <cuda_runtime.h>
#include <cuda_fp16.h>
#include <cstdint>

// ---------------- problem constants ----------------
#define NB   128
#define CCH  3
#define HH   128
#define WW   128
#define LL   4096
#define D1   1204
#define D2   4816
#define MROWS (NB*CCH)          // 384
#define K2P  1280               // D1 padded to multiple of 128
#define SPLITK1 8
#define K1CHUNK (LL/SPLITK1)    // 512
#define EPSV 1e-5f

// prep kernel block partition (exact)
#define NGATHER_BLK (MROWS*LL/256)        // 6144
#define NW1_BLK     (D1*LL/4/256)         // 4816
#define NW2_BLK     (D2*K2P/4/256)        // 6020

// GEMM tile
#define TM 128
#define TN 128
#define TKC 64
#define ROWH 64                 // halves per smem row (128 B)
#define NSTAGES 3

#define TILE_H   (128*ROWH)     // 8192 halves = 16KB
#define A_T_H    0
#define B_T_H    (TILE_H)
#define STAGE_H  (2*TILE_H)     // 32KB
#define SMEM_BYTES (NSTAGES*STAGE_H*2)   // 98304 B -> 2 CTAs/SM

__device__ __forceinline__ uint32_t sw_off(int row, int chunk) {
    return (uint32_t)((row * ROWH + ((chunk ^ (row & 7)) << 3)) * 2);
}

// ---------------- device scratch ----------------
__device__ __align__(16) __half g_sf [MROWS*LL];
__device__ __align__(16) __half g_w1f[D1*LL];
__device__ __align__(16) __half g_w2f[D2*K2P];
__device__ __align__(16) __half g_h1f[MROWS*K2P];
__device__ __align__(16) float g_hp[SPLITK1*MROWS*D1];
__device__ __align__(16) float g_h1[MROWS*D1];
__device__ __align__(16) float g_h2[MROWS*D2];
__device__ float g_stat1[6];
__device__ float g_stat2[6];

// ---------------- PTX helpers ----------------
__device__ __forceinline__ uint32_t smem_to_u32(const void* p) {
    uint32_t a;
    asm("{ .reg .u64 t; cvta.to.shared.u64 t, %1; cvt.u32.u64 %0, t; }" : "=r"(a) : "l"(p));
    return a;
}
__device__ __forceinline__ void cp16(uint32_t saddr, const void* g, int bytes) {
    asm volatile("cp.async.cg.shared.global [%0], [%1], 16, %2;"
                 :: "r"(saddr), "l"(g), "r"(bytes));
}
#define CP_COMMIT() asm volatile("cp.async.commit_group;" ::: "memory")
#define CP_WAIT(N)  asm volatile("cp.async.wait_group %0;" :: "n"(N) : "memory")

__device__ __forceinline__ void ldsm4(uint32_t* r, uint32_t addr) {
    asm volatile("ldmatrix.sync.aligned.m8n8.x4.shared.b16 {%0,%1,%2,%3}, [%4];"
        : "=r"(r[0]), "=r"(r[1]), "=r"(r[2]), "=r"(r[3]) : "r"(addr));
}
__device__ __forceinline__ void mma_f16(float* c, const uint32_t* a, const uint32_t* b) {
    asm volatile(
        "mma.sync.aligned.m16n8k16.row.col.f32.f16.f16.f32 "
        "{%0,%1,%2,%3}, {%4,%5,%6,%7}, {%8,%9}, {%0,%1,%2,%3};"
        : "+f"(c[0]), "+f"(c[1]), "+f"(c[2]), "+f"(c[3])
        : "r"(a[0]), "r"(a[1]), "r"(a[2]), "r"(a[3]), "r"(b[0]), "r"(b[1]));
}

__device__ __forceinline__ uint2 pack4h(const float* v) {
    __half h[4];
    #pragma unroll
    for (int j = 0; j < 4; j++) h[j] = __float2half_rn(v[j]);
    uint2 u;
    u.x = (uint32_t)__half_as_ushort(h[0]) | ((uint32_t)__half_as_ushort(h[1]) << 16);
    u.y = (uint32_t)__half_as_ushort(h[2]) | ((uint32_t)__half_as_ushort(h[3]) << 16);
    return u;
}

// ---------------- fused prep: gather+mask | W1 convert | W2 convert ----------------
__global__ void prep_kernel(const float* __restrict__ x,
                            const int*   __restrict__ coords,
                            const float* __restrict__ mask,
                            const float* __restrict__ W1p,
                            const float* __restrict__ W2p)
{
    int b = blockIdx.x;
    if (b < NGATHER_BLK) {
        if (b == 0 && threadIdx.x < 6) g_stat1[threadIdx.x] = 0.0f;
        int idx = b * 256 + threadIdx.x;
        int l = idx & (LL - 1);
        int m = idx >> 12;
        int n = m / 3;
        int off = coords[2*l] * WW + coords[2*l + 1];
        float v = x[(size_t)m * (HH*WW) + off];
        if (mask[(size_t)n * LL + l] < 0.3f) v = 0.0f;
        g_sf[idx] = __float2half_rn(v);
        return;
    }
    const float* in; int K, ldOut; __half* outh; long q;
    if (b < NGATHER_BLK + NW1_BLK) {
        in = W1p; K = LL; ldOut = LL; outh = g_w1f;
        q = (long)(b - NGATHER_BLK) * 256 + threadIdx.x;
    } else {
        in = W2p; K = D1; ldOut = K2P; outh = g_w2f;
        q = (long)(b - NGATHER_BLK - NW1_BLK) * 256 + threadIdx.x;
    }
    long idx = q * 4;
    int r = (int)(idx / ldOut);
    int c = (int)(idx % ldOut);
    float v[4];
    if (c + 3 < K) {
        float4 f = *reinterpret_cast<const float4*>(in + (size_t)r * K + c);
        v[0] = f.x; v[1] = f.y; v[2] = f.z; v[3] = f.w;
    } else {
        #pragma unroll
        for (int j = 0; j < 4; j++)
            v[j] = (c + j < K) ? in[(size_t)r * K + c + j] : 0.0f;
    }
    *reinterpret_cast<uint2*>(outh + idx) = pack4h(v);
}

// ---------------- mma.sync fp16 GEMM ----------------
// fuseEpi=0: write raw partials (split-K). fuseEpi=1: bias+leaky+stats epilogue.
__global__ __launch_bounds__(256, 2)
void gemm_f16(const __half* __restrict__ A, int lda,
              const __half* __restrict__ B, int ldb, int Brows,
              float* __restrict__ C, int Ncols, int ldc,
              int kLen, size_t zStride,
              const float* __restrict__ colBias, float* __restrict__ gstat,
              int fuseEpi)
{
    extern __shared__ __align__(16) __half smem[];
    uint32_t smem_u32 = smem_to_u32(smem);

    int tid  = threadIdx.x;
    int wid  = tid >> 5;
    int lane = tid & 31;
    int m0 = blockIdx.y * TM;
    int n0 = blockIdx.x * TN;
    C += (size_t)blockIdx.z * zStride;
    int k0 = blockIdx.z * kLen;
    int nIter = kLen / TKC;

    int wm = (wid & 1) * 64;
    int wn = (wid >> 1) * 32;

    float acc[4][4][4];
    #pragma unroll
    for (int i = 0; i < 4; i++)
        #pragma unroll
        for (int j = 0; j < 4; j++)
            #pragma unroll
            for (int q = 0; q < 4; q++) acc[i][j][q] = 0.0f;

    auto load_stage = [&](int stage, int kt) {
        int kbase = k0 + kt * TKC;
        uint32_t sbase = smem_u32 + (uint32_t)stage * STAGE_H * 2;
        #pragma unroll
        for (int it = 0; it < 4; it++) {
            int c = tid + it * 256;
            int row = c >> 3;
            int c16 = c & 7;
            uint32_t so = sw_off(row, c16);
            size_t ao = (size_t)(m0 + row) * lda + kbase + c16 * 8;
            cp16(sbase + A_T_H*2 + so, A + ao, 16);
            int brow = n0 + row;
            int bytes = (brow < Brows) ? 16 : 0;
            int rcl = (brow < Brows) ? brow : (Brows - 1);
            size_t bo = (size_t)rcl * ldb + kbase + c16 * 8;
            cp16(sbase + B_T_H*2 + so, B + bo, bytes);
        }
    };

    #pragma unroll
    for (int p = 0; p < NSTAGES - 1; p++) { load_stage(p, p); CP_COMMIT(); }

    int rowA = lane & 15;
    int chA  = lane >> 4;
    int r8  = lane & 7;
    int grp = lane >> 3;
    int rowB = ((grp & 1) << 3) + r8;
    int chB  = grp >> 1;

    for (int kt = 0; kt < nIter; kt++) {
        CP_WAIT(NSTAGES - 2);
        __syncthreads();
        if (kt + NSTAGES - 1 < nIter) { load_stage((kt + NSTAGES - 1) % NSTAGES, kt + NSTAGES - 1); CP_COMMIT(); }

        uint32_t sbase = smem_u32 + (uint32_t)(kt % NSTAGES) * STAGE_H * 2;
        #pragma unroll
        for (int s = 0; s < TKC/16; s++) {
            int kchunk = s * 2;
            uint32_t ah[4][4], bh[4][2];
            #pragma unroll
            for (int mi = 0; mi < 4; mi++) {
                int row = wm + mi*16 + rowA;
                uint32_t off = sw_off(row, kchunk + chA);
                ldsm4(ah[mi], sbase + A_T_H*2 + off);
            }
            #pragma unroll
            for (int nh = 0; nh < 2; nh++) {
                int row = wn + nh*16 + rowB;
                uint32_t off = sw_off(row, kchunk + chB);
                uint32_t t[4];
                ldsm4(t, sbase + B_T_H*2 + off);
                bh[nh*2][0] = t[0]; bh[nh*2][1] = t[2];
                bh[nh*2+1][0] = t[1]; bh[nh*2+1][1] = t[3];
            }
            #pragma unroll
            for (int mi = 0; mi < 4; mi++)
                #pragma unroll
                for (int ni = 0; ni < 4; ni++)
                    mma_f16(acc[mi][ni], ah[mi], bh[ni]);
        }
        __syncthreads();
    }

    if (!fuseEpi) {
        #pragma unroll
        for (int mi = 0; mi < 4; mi++) {
            int r0 = m0 + wm + mi*16 + (lane >> 2);
            #pragma unroll
            for (int ni = 0; ni < 4; ni++) {
                int c0 = n0 + wn + ni*8 + (lane & 3)*2;
                if (c0 < Ncols) {
                    *reinterpret_cast<float2*>(C + (size_t)r0 * ldc + c0)
                        = make_float2(acc[mi][ni][0], acc[mi][ni][1]);
                    *reinterpret_cast<float2*>(C + (size_t)(r0 + 8) * ldc + c0)
                        = make_float2(acc[mi][ni][2], acc[mi][ni][3]);
                }
            }
        }
        return;
    }

    // ---- fused epilogue: bias + leaky + store + per-channel stats ----
    __shared__ float shs[3], shq[3];
    if (tid < 3) { shs[tid] = 0.0f; shq[tid] = 0.0f; }
    __syncthreads();

    float sacc[3] = {0.0f, 0.0f, 0.0f};
    float qacc[3] = {0.0f, 0.0f, 0.0f};
    #pragma unroll
    for (int mi = 0; mi < 4; mi++) {
        int r0 = m0 + wm + mi*16 + (lane >> 2);
        int ch0 = r0 % 3;
        int ch1 = (r0 + 8) % 3;
        #pragma unroll
        for (int ni = 0; ni < 4; ni++) {
            int c0 = n0 + wn + ni*8 + (lane & 3)*2;
            if (c0 < Ncols) {
                float2 bb = *reinterpret_cast<const float2*>(colBias + c0);
                float2 v0 = make_float2(acc[mi][ni][0] + bb.x, acc[mi][ni][1] + bb.y);
                float2 v1 = make_float2(acc[mi][ni][2] + bb.x, acc[mi][ni][3] + bb.y);
                v0.x = (v0.x >= 0.0f) ? v0.x : 0.01f * v0.x;
                v0.y = (v0.y >= 0.0f) ? v0.y : 0.01f * v0.y;
                v1.x = (v1.x >= 0.0f) ? v1.x : 0.01f * v1.x;
                v1.y = (v1.y >= 0.0f) ? v1.y : 0.01f * v1.y;
                *reinterpret_cast<float2*>(C + (size_t)r0 * ldc + c0) = v0;
                *reinterpret_cast<float2*>(C + (size_t)(r0 + 8) * ldc + c0) = v1;
                sacc[ch0] += v0.x + v0.y;
                qacc[ch0] += v0.x*v0.x + v0.y*v0.y;
                sacc[ch1] += v1.x + v1.y;
                qacc[ch1] += v1.x*v1.x + v1.y*v1.y;
            }
        }
    }
    #pragma unroll
    for (int c = 0; c < 3; c++) {
        float sc = sacc[c], qc = qacc[c];
        #pragma unroll
        for (int o = 16; o; o >>= 1) {
            sc += __shfl_xor_sync(0xffffffffu, sc, o);
            qc += __shfl_xor_sync(0xffffffffu, qc, o);
        }
        if (lane == 0) {
            atomicAdd(&shs[c], sc);
            atomicAdd(&shq[c], qc);
        }
    }
    __syncthreads();
    if (tid < 3) {
        atomicAdd(&gstat[tid],     shs[tid]);
        atomicAdd(&gstat[3 + tid], shq[tid]);
    }
}

// ---------------- combine + bias + leaky + BN stats (GEMM1 split-K only) ----------------
__global__ void combine_kernel(const float* __restrict__ bias,
                               float* __restrict__ outp, int Ncols, int nparts,
                               float* __restrict__ gstat)
{
    __shared__ float shs[3], shq[3];
    if (threadIdx.x < 3) { shs[threadIdx.x] = 0.0f; shq[threadIdx.x] = 0.0f; }
    __syncthreads();

    int i4 = blockIdx.x * blockDim.x + threadIdx.x;
    int total4 = MROWS * Ncols / 4;
    bool active = (i4 < total4);
    float s = 0.0f, q = 0.0f;
    int ch = 0;
    if (active) {
        int idx = i4 * 4;
        const int MN = MROWS * Ncols;
        float4 v = *reinterpret_cast<const float4*>(g_hp + idx);
        for (int p = 1; p < nparts; p++) {
            float4 a = *reinterpret_cast<const float4*>(g_hp + (size_t)p * MN + idx);
            v.x += a.x; v.y += a.y; v.z += a.z; v.w += a.w;
        }
        float4 bb = *reinterpret_cast<const float4*>(bias + (idx % Ncols));
        v.x += bb.x; v.y += bb.y; v.z += bb.z; v.w += bb.w;
        v.x = (v.x >= 0.0f) ? v.x : 0.01f * v.x;
        v.y = (v.y >= 0.0f) ? v.y : 0.01f * v.y;
        v.z = (v.z >= 0.0f) ? v.z : 0.01f * v.z;
        v.w = (v.w >= 0.0f) ? v.w : 0.01f * v.w;
        *reinterpret_cast<float4*>(outp + idx) = v;
        ch = (idx / Ncols) % 3;
        s = v.x + v.y + v.z + v.w;
        q = v.x*v.x + v.y*v.y + v.z*v.z + v.w*v.w;
    }
    int lane = threadIdx.x & 31;
    #pragma unroll
    for (int c = 0; c < 3; c++) {
        float sc = (active && ch == c) ? s : 0.0f;
        float qc = (active && ch == c) ? q : 0.0f;
        #pragma unroll
        for (int o = 16; o; o >>= 1) {
            sc += __shfl_xor_sync(0xffffffffu, sc, o);
            qc += __shfl_xor_sync(0xffffffffu, qc, o);
        }
        if (lane == 0) {
            atomicAdd(&shs[c], sc);
            atomicAdd(&shq[c], qc);
        }
    }
    __syncthreads();
    if (threadIdx.x < 3) {
        atomicAdd(&gstat[threadIdx.x],     shs[threadIdx.x]);
        atomicAdd(&gstat[3 + threadIdx.x], shq[threadIdx.x]);
    }
}

// ---------------- h1 -> BN1 affine inline -> fp16, padded to K2P (zeroes stat2) ----------------
__global__ void convert_h1_kernel(const float* __restrict__ gamma,
                                  const float* __restrict__ beta)
{
    if (blockIdx.x == 0 && threadIdx.x < 6) g_stat2[threadIdx.x] = 0.0f;
    int i4 = blockIdx.x * blockDim.x + threadIdx.x;
    if (i4 >= MROWS * K2P / 4) return;
    int idx = i4 * 4;
    int r = idx / K2P;
    int c = idx % K2P;
    int ch = r % 3;
    float cnt = (float)NB * (float)D1;
    float mean = g_stat1[ch] / cnt;
    float var  = g_stat1[3 + ch] / cnt - mean * mean;
    float a = gamma[ch] * rsqrtf(var + EPSV);
    float b = beta[ch] - mean * a;
    float v[4] = {0.0f, 0.0f, 0.0f, 0.0f};
    if (c + 3 < D1) {
        float4 f = *reinterpret_cast<const float4*>(g_h1 + (size_t)r * D1 + c);
        v[0] = f.x * a + b; v[1] = f.y * a + b; v[2] = f.z * a + b; v[3] = f.w * a + b;
    } else {
        #pragma unroll
        for (int j = 0; j < 4; j++)
            if (c + j < D1) v[j] = g_h1[(size_t)r * D1 + c + j] * a + b;
    }
    *reinterpret_cast<uint2*>(g_h1f + idx) = pack4h(v);
}

// ---------------- final BN2 affine inline -> output ----------------
__global__ void final_kernel(const float* __restrict__ gamma,
                             const float* __restrict__ beta,
                             float* __restrict__ out)
{
    int i4 = blockIdx.x * blockDim.x + threadIdx.x;
    if (i4 >= MROWS * D2 / 4) return;
    int idx = i4 * 4;
    int ch = (idx / D2) % 3;
    float cnt = (float)NB * (float)D2;
    float mean = g_stat2[ch] / cnt;
    float var  = g_stat2[3 + ch] / cnt - mean * mean;
    float a = gamma[ch] * rsqrtf(var + EPSV);
    float b = beta[ch] - mean * a;
    float4 v = *reinterpret_cast<const float4*>(g_h2 + idx);
    v.x = v.x * a + b; v.y = v.y * a + b; v.z = v.z * a + b; v.w = v.w * a + b;
    *reinterpret_cast<float4*>(out + idx) = v;
}

// ---------------- launch ----------------
extern "C" void kernel_launch(void* const* d_in, const int* in_sizes, int n_in,
                              void* d_out, int out_size)
{
    const float* x      = (const float*)d_in[0];
    const int*   coords = (const int*)  d_in[1];
    const float* mask   = (const float*)d_in[2];
    const float* W1     = (const float*)d_in[3];
    const float* b1     = (const float*)d_in[4];
    const float* g1     = (const float*)d_in[5];
    const float* be1    = (const float*)d_in[6];
    const float* W2     = (const float*)d_in[7];
    const float* b2     = (const float*)d_in[8];
    const float* g2     = (const float*)d_in[9];
    const float* be2    = (const float*)d_in[10];
    float* out = (float*)d_out;

    static bool inited = false;
    static __half *p_sf, *p_w1f, *p_w2f, *p_h1f;
    static float *p_hp, *p_h1, *p_h2, *p_s1, *p_s2;
    if (!inited) {
        cudaGetSymbolAddress((void**)&p_sf,  g_sf);
        cudaGetSymbolAddress((void**)&p_w1f, g_w1f);
        cudaGetSymbolAddress((void**)&p_w2f, g_w2f);
        cudaGetSymbolAddress((void**)&p_h1f, g_h1f);
        cudaGetSymbolAddress((void**)&p_hp,  g_hp);
        cudaGetSymbolAddress((void**)&p_h1,  g_h1);
        cudaGetSymbolAddress((void**)&p_h2,  g_h2);
        cudaGetSymbolAddress((void**)&p_s1,  g_stat1);
        cudaGetSymbolAddress((void**)&p_s2,  g_stat2);
        cudaFuncSetAttribute(gemm_f16, cudaFuncAttributeMaxDynamicSharedMemorySize, SMEM_BYTES);
        inited = true;
    }

    // 1) fused prep: gather | W1 convert | W2 convert
    prep_kernel<<<NGATHER_BLK + NW1_BLK + NW2_BLK, 256>>>(x, coords, mask, W1, W2);

    // 2) GEMM1 split-K=8 -> partials
    {
        dim3 grid((D1 + TN - 1) / TN, MROWS / TM, SPLITK1);  // 240 CTAs
        gemm_f16<<<grid, 256, SMEM_BYTES>>>(
            p_sf, LL,
            p_w1f, LL, D1,
            p_hp, D1, D1,
            K1CHUNK, (size_t)MROWS * D1,
            nullptr, nullptr, 0);
    }

    // 3) combine(8) + b1 + leaky -> h1, fused BN1 stats
    combine_kernel<<<(MROWS*D1/4 + 255) / 256, 256>>>(b1, p_h1, D1, SPLITK1, p_s1);

    // 4) affine1 inline + h1 fp16 conversion (zeroes stat2)
    convert_h1_kernel<<<(MROWS*K2P/4 + 255) / 256, 256>>>(g1, be1);

    // 5) GEMM2 split-K=1, fused epilogue: bias + leaky + h2 + BN2 stats
    {
        dim3 grid((D2 + TN - 1) / TN, MROWS / TM, 1);        // 114 CTAs
        gemm_f16<<<grid, 256, SMEM_BYTES>>>(
            p_h1f, K2P,
            p_w2f, K2P, D2,
            p_h2, D2, D2,
            K2P, 0,
            b2, p_s2, 1);
    }

    // 6) affine2 inline -> out
    final_kernel<<<(MROWS*D2/4 + 255) / 256, 256>>>(g2, be2, out);
}

// round 16
// speedup vs baseline: 1.0229x; 1.0229x over previous
#include <cuda_runtime.h>
#include <cuda_fp16.h>
#include <cstdint>

// ---------------- problem constants ----------------
#define NB   128
#define CCH  3
#define HH   128
#define WW   128
#define LL   4096
#define D1   1204
#define D2   4816
#define MROWS (NB*CCH)          // 384
#define K2P  1280               // D1 padded to multiple of 128
#define SPLITK1 8
#define SPLITK2 2
#define K1CHUNK (LL/SPLITK1)    // 512
#define K2CHUNK (K2P/SPLITK2)   // 640
#define EPSV 1e-5f

// prep kernel block partition (exact)
#define NGATHER_BLK (MROWS*LL/256)        // 6144
#define NW1_BLK     (D1*LL/4/256)         // 4816
#define NW2_BLK     (D2*K2P/4/256)        // 6020

// fused combine grids
#define NB1BLK 452                        // ceil(115584/256); minblocks 4 -> 592 resident >= 452
#define NB2BLK 288                        // minblocks 2 -> 296 resident >= 288
#define CHUNK2 7                          // ceil(462336 / (288*256))

// GEMM tile (R14 proven)
#define TM 128
#define TN 128
#define TKC 64
#define ROWH 64
#define NSTAGES 3

#define TILE_H   (128*ROWH)
#define A_T_H    0
#define B_T_H    (TILE_H)
#define STAGE_H  (2*TILE_H)
#define SMEM_BYTES (NSTAGES*STAGE_H*2)   // 98304 B -> 2 CTAs/SM

__device__ __forceinline__ uint32_t sw_off(int row, int chunk) {
    return (uint32_t)((row * ROWH + ((chunk ^ (row & 7)) << 3)) * 2);
}

// ---------------- device scratch ----------------
__device__ __align__(16) __half g_sf [MROWS*LL];
__device__ __align__(16) __half g_w1f[D1*LL];
__device__ __align__(16) __half g_w2f[D2*K2P];
__device__ __align__(16) __half g_h1f[MROWS*K2P];   // pad cols stay zero (static init)
__device__ __align__(16) float g_hp[SPLITK1*MROWS*D1];  // == SPLITK2*MROWS*D2
__device__ float g_stat1[6];
__device__ float g_stat2[6];
__device__ int   g_bar1[3];   // arrive, flag, done
__device__ int   g_bar2[3];

// ---------------- PTX helpers ----------------
__device__ __forceinline__ uint32_t smem_to_u32(const void* p) {
    uint32_t a;
    asm("{ .reg .u64 t; cvta.to.shared.u64 t, %1; cvt.u32.u64 %0, t; }" : "=r"(a) : "l"(p));
    return a;
}
__device__ __forceinline__ void cp16(uint32_t saddr, const void* g, int bytes) {
    asm volatile("cp.async.cg.shared.global [%0], [%1], 16, %2;"
                 :: "r"(saddr), "l"(g), "r"(bytes));
}
#define CP_COMMIT() asm volatile("cp.async.commit_group;" ::: "memory")
#define CP_WAIT(N)  asm volatile("cp.async.wait_group %0;" :: "n"(N) : "memory")

__device__ __forceinline__ void ldsm4(uint32_t* r, uint32_t addr) {
    asm volatile("ldmatrix.sync.aligned.m8n8.x4.shared.b16 {%0,%1,%2,%3}, [%4];"
        : "=r"(r[0]), "=r"(r[1]), "=r"(r[2]), "=r"(r[3]) : "r"(addr));
}
__device__ __forceinline__ void mma_f16(float* c, const uint32_t* a, const uint32_t* b) {
    asm volatile(
        "mma.sync.aligned.m16n8k16.row.col.f32.f16.f16.f32 "
        "{%0,%1,%2,%3}, {%4,%5,%6,%7}, {%8,%9}, {%0,%1,%2,%3};"
        : "+f"(c[0]), "+f"(c[1]), "+f"(c[2]), "+f"(c[3])
        : "r"(a[0]), "r"(a[1]), "r"(a[2]), "r"(a[3]), "r"(b[0]), "r"(b[1]));
}

__device__ __forceinline__ uint2 pack4h(const float* v) {
    __half h[4];
    #pragma unroll
    for (int j = 0; j < 4; j++) h[j] = __float2half_rn(v[j]);
    uint2 u;
    u.x = (uint32_t)__half_as_ushort(h[0]) | ((uint32_t)__half_as_ushort(h[1]) << 16);
    u.y = (uint32_t)__half_as_ushort(h[2]) | ((uint32_t)__half_as_ushort(h[3]) << 16);
    return u;
}

// grid barrier (thread 0 per block). All blocks guaranteed co-resident by launch bounds.
__device__ __forceinline__ void grid_barrier(int* bar, int nblocks) {
    __threadfence();
    if (threadIdx.x == 0) {
        int old = atomicAdd(&bar[0], 1);
        if (old == nblocks - 1) atomicExch(&bar[1], 1);
        else while (atomicAdd(&bar[1], 0) == 0) __nanosleep(64);
    }
    __syncthreads();
}
__device__ __forceinline__ void grid_barrier_reset(int* bar, int nblocks) {
    if (threadIdx.x == 0) {
        int d = atomicAdd(&bar[2], 1);
        if (d == nblocks - 1) { bar[0] = 0; bar[1] = 0; bar[2] = 0; }
    }
}

// ---------------- fused prep: gather+mask | W1 convert | W2 convert ----------------
__global__ void prep_kernel(const float* __restrict__ x,
                            const int*   __restrict__ coords,
                            const float* __restrict__ mask,
                            const float* __restrict__ W1p,
                            const float* __restrict__ W2p)
{
    int b = blockIdx.x;
    if (b < NGATHER_BLK) {
        if (b == 0 && threadIdx.x < 6) { g_stat1[threadIdx.x] = 0.0f; g_stat2[threadIdx.x] = 0.0f; }
        int idx = b * 256 + threadIdx.x;
        int l = idx & (LL - 1);
        int m = idx >> 12;
        int n = m / 3;
        int off = coords[2*l] * WW + coords[2*l + 1];
        float v = x[(size_t)m * (HH*WW) + off];
        if (mask[(size_t)n * LL + l] < 0.3f) v = 0.0f;
        g_sf[idx] = __float2half_rn(v);
        return;
    }
    const float* in; int K, ldOut; __half* outh; long q;
    if (b < NGATHER_BLK + NW1_BLK) {
        in = W1p; K = LL; ldOut = LL; outh = g_w1f;
        q = (long)(b - NGATHER_BLK) * 256 + threadIdx.x;
    } else {
        in = W2p; K = D1; ldOut = K2P; outh = g_w2f;
        q = (long)(b - NGATHER_BLK - NW1_BLK) * 256 + threadIdx.x;
    }
    long idx = q * 4;
    int r = (int)(idx / ldOut);
    int c = (int)(idx % ldOut);
    float v[4];
    if (c + 3 < K) {
        float4 f = *reinterpret_cast<const float4*>(in + (size_t)r * K + c);
        v[0] = f.x; v[1] = f.y; v[2] = f.z; v[3] = f.w;
    } else {
        #pragma unroll
        for (int j = 0; j < 4; j++)
            v[j] = (c + j < K) ? in[(size_t)r * K + c + j] : 0.0f;
    }
    *reinterpret_cast<uint2*>(outh + idx) = pack4h(v);
}

// ---------------- mma.sync fp16 GEMM (R14 verbatim) ----------------
__global__ __launch_bounds__(256, 2)
void gemm_f16(const __half* __restrict__ A, int lda,
              const __half* __restrict__ B, int ldb, int Brows,
              float* __restrict__ C, int Ncols, int ldc,
              int kLen, size_t zStride)
{
    extern __shared__ __align__(16) __half smem[];
    uint32_t smem_u32 = smem_to_u32(smem);

    int tid  = threadIdx.x;
    int wid  = tid >> 5;
    int lane = tid & 31;
    int m0 = blockIdx.y * TM;
    int n0 = blockIdx.x * TN;
    C += (size_t)blockIdx.z * zStride;
    int k0 = blockIdx.z * kLen;
    int nIter = kLen / TKC;

    int wm = (wid & 1) * 64;
    int wn = (wid >> 1) * 32;

    float acc[4][4][4];
    #pragma unroll
    for (int i = 0; i < 4; i++)
        #pragma unroll
        for (int j = 0; j < 4; j++)
            #pragma unroll
            for (int q = 0; q < 4; q++) acc[i][j][q] = 0.0f;

    auto load_stage = [&](int stage, int kt) {
        int kbase = k0 + kt * TKC;
        uint32_t sbase = smem_u32 + (uint32_t)stage * STAGE_H * 2;
        #pragma unroll
        for (int it = 0; it < 4; it++) {
            int c = tid + it * 256;
            int row = c >> 3;
            int c16 = c & 7;
            uint32_t so = sw_off(row, c16);
            size_t ao = (size_t)(m0 + row) * lda + kbase + c16 * 8;
            cp16(sbase + A_T_H*2 + so, A + ao, 16);
            int brow = n0 + row;
            int bytes = (brow < Brows) ? 16 : 0;
            int rcl = (brow < Brows) ? brow : (Brows - 1);
            size_t bo = (size_t)rcl * ldb + kbase + c16 * 8;
            cp16(sbase + B_T_H*2 + so, B + bo, bytes);
        }
    };

    #pragma unroll
    for (int p = 0; p < NSTAGES - 1; p++) { load_stage(p, p); CP_COMMIT(); }

    int rowA = lane & 15;
    int chA  = lane >> 4;
    int r8  = lane & 7;
    int grp = lane >> 3;
    int rowB = ((grp & 1) << 3) + r8;
    int chB  = grp >> 1;

    for (int kt = 0; kt < nIter; kt++) {
        CP_WAIT(NSTAGES - 2);
        __syncthreads();
        if (kt + NSTAGES - 1 < nIter) { load_stage((kt + NSTAGES - 1) % NSTAGES, kt + NSTAGES - 1); CP_COMMIT(); }

        uint32_t sbase = smem_u32 + (uint32_t)(kt % NSTAGES) * STAGE_H * 2;
        #pragma unroll
        for (int s = 0; s < TKC/16; s++) {
            int kchunk = s * 2;
            uint32_t ah[4][4], bh[4][2];
            #pragma unroll
            for (int mi = 0; mi < 4; mi++) {
                int row = wm + mi*16 + rowA;
                uint32_t off = sw_off(row, kchunk + chA);
                ldsm4(ah[mi], sbase + A_T_H*2 + off);
            }
            #pragma unroll
            for (int nh = 0; nh < 2; nh++) {
                int row = wn + nh*16 + rowB;
                uint32_t off = sw_off(row, kchunk + chB);
                uint32_t t[4];
                ldsm4(t, sbase + B_T_H*2 + off);
                bh[nh*2][0] = t[0]; bh[nh*2][1] = t[2];
                bh[nh*2+1][0] = t[1]; bh[nh*2+1][1] = t[3];
            }
            #pragma unroll
            for (int mi = 0; mi < 4; mi++)
                #pragma unroll
                for (int ni = 0; ni < 4; ni++)
                    mma_f16(acc[mi][ni], ah[mi], bh[ni]);
        }
        __syncthreads();
    }

    #pragma unroll
    for (int mi = 0; mi < 4; mi++) {
        int r0 = m0 + wm + mi*16 + (lane >> 2);
        #pragma unroll
        for (int ni = 0; ni < 4; ni++) {
            int c0 = n0 + wn + ni*8 + (lane & 3)*2;
            if (c0 < Ncols) {
                *reinterpret_cast<float2*>(C + (size_t)r0 * ldc + c0)
                    = make_float2(acc[mi][ni][0], acc[mi][ni][1]);
                *reinterpret_cast<float2*>(C + (size_t)(r0 + 8) * ldc + c0)
                    = make_float2(acc[mi][ni][2], acc[mi][ni][3]);
            }
        }
    }
}

// ---------------- fused combine1: sum+bias+leaky+stats -> barrier -> affine1 -> fp16 h1f ----------------
__global__ __launch_bounds__(256, 4)
void fused_combine1(const float* __restrict__ bias,
                    const float* __restrict__ gamma,
                    const float* __restrict__ beta)
{
    __shared__ float shs[3], shq[3];
    if (threadIdx.x < 3) { shs[threadIdx.x] = 0.0f; shq[threadIdx.x] = 0.0f; }
    __syncthreads();

    const int total4 = MROWS * D1 / 4;
    int i4 = blockIdx.x * blockDim.x + threadIdx.x;
    bool active = (i4 < total4);
    float v[4] = {0.0f, 0.0f, 0.0f, 0.0f};
    int r = 0, c = 0, ch = 0;
    float s = 0.0f, q = 0.0f;
    if (active) {
        int idx = i4 * 4;
        r = idx / D1; c = idx % D1; ch = r % 3;
        const int MN = MROWS * D1;
        float4 a0 = *reinterpret_cast<const float4*>(g_hp + idx);
        v[0] = a0.x; v[1] = a0.y; v[2] = a0.z; v[3] = a0.w;
        for (int p = 1; p < SPLITK1; p++) {
            float4 a = *reinterpret_cast<const float4*>(g_hp + (size_t)p * MN + idx);
            v[0] += a.x; v[1] += a.y; v[2] += a.z; v[3] += a.w;
        }
        float4 bb = *reinterpret_cast<const float4*>(bias + c);
        v[0] += bb.x; v[1] += bb.y; v[2] += bb.z; v[3] += bb.w;
        #pragma unroll
        for (int j = 0; j < 4; j++) {
            v[j] = (v[j] >= 0.0f) ? v[j] : 0.01f * v[j];
            s += v[j]; q += v[j] * v[j];
        }
    }
    int lane = threadIdx.x & 31;
    #pragma unroll
    for (int cc = 0; cc < 3; cc++) {
        float sc = (active && ch == cc) ? s : 0.0f;
        float qc = (active && ch == cc) ? q : 0.0f;
        #pragma unroll
        for (int o = 16; o; o >>= 1) {
            sc += __shfl_xor_sync(0xffffffffu, sc, o);
            qc += __shfl_xor_sync(0xffffffffu, qc, o);
        }
        if (lane == 0) { atomicAdd(&shs[cc], sc); atomicAdd(&shq[cc], qc); }
    }
    __syncthreads();
    if (threadIdx.x < 3) {
        atomicAdd(&g_stat1[threadIdx.x],     shs[threadIdx.x]);
        atomicAdd(&g_stat1[3 + threadIdx.x], shq[threadIdx.x]);
    }

    grid_barrier(g_bar1, NB1BLK);

    if (active) {
        float cnt = (float)NB * (float)D1;
        float mean = __ldcg(&g_stat1[ch]) / cnt;
        float var  = __ldcg(&g_stat1[3 + ch]) / cnt - mean * mean;
        float a = __ldg(&gamma[ch]) * rsqrtf(var + EPSV);
        float b = __ldg(&beta[ch]) - mean * a;
        float w[4];
        #pragma unroll
        for (int j = 0; j < 4; j++) w[j] = v[j] * a + b;
        *reinterpret_cast<uint2*>(g_h1f + (size_t)r * K2P + c) = pack4h(w);
    }
    grid_barrier_reset(g_bar1, NB1BLK);
}

// ---------------- fused combine2: sum+bias+leaky+stats -> barrier -> affine2 -> out ----------------
__global__ __launch_bounds__(256, 2)
void fused_combine2(const float* __restrict__ bias,
                    const float* __restrict__ gamma,
                    const float* __restrict__ beta,
                    float* __restrict__ out)
{
    __shared__ float shs[3], shq[3];
    if (threadIdx.x < 3) { shs[threadIdx.x] = 0.0f; shq[threadIdx.x] = 0.0f; }
    __syncthreads();

    const int total4 = MROWS * D2 / 4;   // 462336
    const int stride = NB2BLK * 256;     // 73728
    int base = blockIdx.x * blockDim.x + threadIdx.x;

    float v[CHUNK2][4];
    float sacc[3] = {0.0f, 0.0f, 0.0f};
    float qacc[3] = {0.0f, 0.0f, 0.0f};
    const int MN = MROWS * D2;

    #pragma unroll
    for (int k = 0; k < CHUNK2; k++) {
        int i4 = base + k * stride;
        if (i4 < total4) {
            int idx = i4 * 4;
            int c = idx % D2;
            int ch = (idx / D2) % 3;
            float4 a0 = *reinterpret_cast<const float4*>(g_hp + idx);
            float4 a1 = *reinterpret_cast<const float4*>(g_hp + (size_t)MN + idx);
            v[k][0] = a0.x + a1.x; v[k][1] = a0.y + a1.y;
            v[k][2] = a0.z + a1.z; v[k][3] = a0.w + a1.w;
            float4 bb = *reinterpret_cast<const float4*>(bias + c);
            v[k][0] += bb.x; v[k][1] += bb.y; v[k][2] += bb.z; v[k][3] += bb.w;
            #pragma unroll
            for (int j = 0; j < 4; j++) {
                v[k][j] = (v[k][j] >= 0.0f) ? v[k][j] : 0.01f * v[k][j];
                sacc[ch] += v[k][j];
                qacc[ch] += v[k][j] * v[k][j];
            }
        }
    }
    int lane = threadIdx.x & 31;
    #pragma unroll
    for (int cc = 0; cc < 3; cc++) {
        float sc = sacc[cc], qc = qacc[cc];
        #pragma unroll
        for (int o = 16; o; o >>= 1) {
            sc += __shfl_xor_sync(0xffffffffu, sc, o);
            qc += __shfl_xor_sync(0xffffffffu, qc, o);
        }
        if (lane == 0) { atomicAdd(&shs[cc], sc); atomicAdd(&shq[cc], qc); }
    }
    __syncthreads();
    if (threadIdx.x < 3) {
        atomicAdd(&g_stat2[threadIdx.x],     shs[threadIdx.x]);
        atomicAdd(&g_stat2[3 + threadIdx.x], shq[threadIdx.x]);
    }

    grid_barrier(g_bar2, NB2BLK);

    float cnt = (float)NB * (float)D2;
    float mean[3], aa[3], bbch[3];
    #pragma unroll
    for (int cc = 0; cc < 3; cc++) {
        mean[cc] = __ldcg(&g_stat2[cc]) / cnt;
        float var = __ldcg(&g_stat2[3 + cc]) / cnt - mean[cc] * mean[cc];
        aa[cc] = __ldg(&gamma[cc]) * rsqrtf(var + EPSV);
        bbch[cc] = __ldg(&beta[cc]) - mean[cc] * aa[cc];
    }
    #pragma unroll
    for (int k = 0; k < CHUNK2; k++) {
        int i4 = base + k * stride;
        if (i4 < total4) {
            int idx = i4 * 4;
            int ch = (idx / D2) % 3;
            float4 w;
            w.x = v[k][0] * aa[ch] + bbch[ch];
            w.y = v[k][1] * aa[ch] + bbch[ch];
            w.z = v[k][2] * aa[ch] + bbch[ch];
            w.w = v[k][3] * aa[ch] + bbch[ch];
            *reinterpret_cast<float4*>(out + idx) = w;
        }
    }
    grid_barrier_reset(g_bar2, NB2BLK);
}

// ---------------- launch ----------------
extern "C" void kernel_launch(void* const* d_in, const int* in_sizes, int n_in,
                              void* d_out, int out_size)
{
    const float* x      = (const float*)d_in[0];
    const int*   coords = (const int*)  d_in[1];
    const float* mask   = (const float*)d_in[2];
    const float* W1     = (const float*)d_in[3];
    const float* b1     = (const float*)d_in[4];
    const float* g1     = (const float*)d_in[5];
    const float* be1    = (const float*)d_in[6];
    const float* W2     = (const float*)d_in[7];
    const float* b2     = (const float*)d_in[8];
    const float* g2     = (const float*)d_in[9];
    const float* be2    = (const float*)d_in[10];
    float* out = (float*)d_out;

    static bool inited = false;
    static __half *p_sf, *p_w1f, *p_w2f, *p_h1f;
    static float *p_hp;
    if (!inited) {
        cudaGetSymbolAddress((void**)&p_sf,  g_sf);
        cudaGetSymbolAddress((void**)&p_w1f, g_w1f);
        cudaGetSymbolAddress((void**)&p_w2f, g_w2f);
        cudaGetSymbolAddress((void**)&p_h1f, g_h1f);
        cudaGetSymbolAddress((void**)&p_hp,  g_hp);
        cudaFuncSetAttribute(gemm_f16, cudaFuncAttributeMaxDynamicSharedMemorySize, SMEM_BYTES);
        inited = true;
    }

    // 1) fused prep: gather | W1 convert | W2 convert (also zeroes stats)
    prep_kernel<<<NGATHER_BLK + NW1_BLK + NW2_BLK, 256>>>(x, coords, mask, W1, W2);

    // 2) GEMM1 split-K=8 -> partials
    {
        dim3 grid((D1 + TN - 1) / TN, MROWS / TM, SPLITK1);  // 240 CTAs
        gemm_f16<<<grid, 256, SMEM_BYTES>>>(
            p_sf, LL,
            p_w1f, LL, D1,
            p_hp, D1, D1,
            K1CHUNK, (size_t)MROWS * D1);
    }

    // 3) fused combine1: sum + b1 + leaky + BN1 stats -> barrier -> affine1 -> fp16 h1f
    fused_combine1<<<NB1BLK, 256>>>(b1, g1, be1);

    // 4) GEMM2 split-K=2 -> partials
    {
        dim3 grid((D2 + TN - 1) / TN, MROWS / TM, SPLITK2);  // 228 CTAs
        gemm_f16<<<grid, 256, SMEM_BYTES>>>(
            p_h1f, K2P,
            p_w2f, K2P, D2,
            p_hp, D2, D2,
            K2CHUNK, (size_t)MROWS * D2);
    }

    // 5) fused combine2: sum + b2 + leaky + BN2 stats -> barrier -> affine2 -> out
    fused_combine2<<<NB2BLK, 256>>>(b2, g2, be2, out);
}